// round 1
// baseline (speedup 1.0000x reference)
#include <cuda_runtime.h>
#include <cuda_bf16.h>
#include <math_constants.h>

#define D_MODEL 512
#define SRC 256
#define TGT 256
#define LDIM 256
#define NB 8

// ---------------- scratch (no allocation allowed) ----------------
__device__ float g_dt[NB * TGT * LDIM];   // [2048, 256]
__device__ float g_et[NB * SRC * LDIM];   // [2048, 256]

// ---------------- kernel 1: dual projection GEMM -----------------
// C[M,256] = A[M,512] @ W[512,256], M = 2048, z=0 -> dt, z=1 -> et
#define BM 64
#define BN 64
#define BK 16

__global__ __launch_bounds__(256) void proj_kernel(
    const float* __restrict__ dec, const float* __restrict__ enc,
    const float* __restrict__ W1,  const float* __restrict__ W2)
{
    const float* A;
    const float* W;
    float* C;
    if (blockIdx.z == 0) { A = dec; W = W1; C = g_dt; }
    else                 { A = enc; W = W2; C = g_et; }

    __shared__ float As[BK][68];   // padded: conflict-free transposed store, 16B-aligned rows
    __shared__ float Bs[BK][BN];

    const int tid = threadIdx.x;
    const int m0 = blockIdx.y * BM;
    const int n0 = blockIdx.x * BN;
    const int tx = tid & 15;       // n micro index
    const int ty = tid >> 4;       // m micro index

    // loader indices
    const int am = tid >> 2;           // 0..63
    const int ak = (tid & 3) * 4;      // 0,4,8,12
    const int bk = tid >> 4;           // 0..15
    const int bn = (tid & 15) * 4;     // 0..60

    float acc[4][4];
#pragma unroll
    for (int i = 0; i < 4; i++)
#pragma unroll
        for (int j = 0; j < 4; j++) acc[i][j] = 0.0f;

    for (int k0 = 0; k0 < D_MODEL; k0 += BK) {
        float4 av = *(const float4*)(A + (m0 + am) * D_MODEL + k0 + ak);
        float4 bv = *(const float4*)(W + (k0 + bk) * LDIM + n0 + bn);
        As[ak + 0][am] = av.x;
        As[ak + 1][am] = av.y;
        As[ak + 2][am] = av.z;
        As[ak + 3][am] = av.w;
        *(float4*)&Bs[bk][bn] = bv;
        __syncthreads();
#pragma unroll
        for (int k = 0; k < BK; k++) {
            float4 a = *(const float4*)&As[k][ty * 4];
            float4 b = *(const float4*)&Bs[k][tx * 4];
            acc[0][0] = fmaf(a.x, b.x, acc[0][0]);
            acc[0][1] = fmaf(a.x, b.y, acc[0][1]);
            acc[0][2] = fmaf(a.x, b.z, acc[0][2]);
            acc[0][3] = fmaf(a.x, b.w, acc[0][3]);
            acc[1][0] = fmaf(a.y, b.x, acc[1][0]);
            acc[1][1] = fmaf(a.y, b.y, acc[1][1]);
            acc[1][2] = fmaf(a.y, b.z, acc[1][2]);
            acc[1][3] = fmaf(a.y, b.w, acc[1][3]);
            acc[2][0] = fmaf(a.z, b.x, acc[2][0]);
            acc[2][1] = fmaf(a.z, b.y, acc[2][1]);
            acc[2][2] = fmaf(a.z, b.z, acc[2][2]);
            acc[2][3] = fmaf(a.z, b.w, acc[2][3]);
            acc[3][0] = fmaf(a.w, b.x, acc[3][0]);
            acc[3][1] = fmaf(a.w, b.y, acc[3][1]);
            acc[3][2] = fmaf(a.w, b.z, acc[3][2]);
            acc[3][3] = fmaf(a.w, b.w, acc[3][3]);
        }
        __syncthreads();
    }

#pragma unroll
    for (int i = 0; i < 4; i++) {
        float4 o = make_float4(acc[i][0], acc[i][1], acc[i][2], acc[i][3]);
        *(float4*)(C + (m0 + ty * 4 + i) * LDIM + n0 + tx * 4) = o;
    }
}

// ---------------- kernel 2: fused score + mask + log_softmax -----
// block = (t_tile of TT, b); thread j = src position s.
#define TT 8
#define CL 32

__global__ __launch_bounds__(256) void score_kernel(
    const int* __restrict__ lens, const float* __restrict__ vt,
    float* __restrict__ out)
{
    __shared__ float dt_sh[TT][LDIM];      // reused as score matrix after l-loop
    __shared__ float et_sh[CL][SRC + 1];   // transposed chunk, padded
    __shared__ float vt_sh[LDIM];
    __shared__ float logZ[TT];

    const int b  = blockIdx.y;
    const int t0 = blockIdx.x * TT;
    const int j  = threadIdx.x;            // s index, 0..255

    vt_sh[j] = vt[j];

    // load dt tile: 8 contiguous rows of 256 = 2048 contiguous floats
    {
        const float4* src4 = (const float4*)(g_dt + (b * TGT + t0) * LDIM);
        float4* dst4 = (float4*)&dt_sh[0][0];
        dst4[j]       = src4[j];
        dst4[j + 256] = src4[j + 256];
    }

    float acc[TT];
#pragma unroll
    for (int t = 0; t < TT; t++) acc[t] = 0.0f;

    const float4* et_row = (const float4*)(g_et + (b * SRC + j) * LDIM);

    for (int lc = 0; lc < LDIM; lc += CL) {
        __syncthreads();   // protect et_sh (and first-iter dt/vt visibility)
        // stage et[b][j][lc..lc+31] transposed into smem
#pragma unroll
        for (int q = 0; q < CL / 4; q++) {
            float4 v = et_row[(lc >> 2) + q];
            et_sh[q * 4 + 0][j] = v.x;
            et_sh[q * 4 + 1][j] = v.y;
            et_sh[q * 4 + 2][j] = v.z;
            et_sh[q * 4 + 3][j] = v.w;
        }
        __syncthreads();

#pragma unroll 4
        for (int c = 0; c < CL; c++) {
            float e = et_sh[c][j];
            float v = vt_sh[lc + c];
#pragma unroll
            for (int t = 0; t < TT; t++) {
                float x = dt_sh[t][lc + c] + e;
                float th;
                asm("tanh.approx.f32 %0, %1;" : "=f"(th) : "f"(x));
                acc[t] = fmaf(v, th, acc[t]);
            }
        }
    }

    // mask term: log(1 + eps) -> 0 in fp32 for valid, log(eps) for masked
    const float mterm = logf(((j < lens[b]) ? 1.0f : 0.0f) + 1e-8f);

    __syncthreads();       // done reading dt_sh as dt; reuse as scores
#pragma unroll
    for (int t = 0; t < TT; t++) dt_sh[t][j] = acc[t] + mterm;
    __syncthreads();

    // warp w reduces score row t=w (256 values) -> logZ[w]
    const int w = j >> 5, lane = j & 31;
    {
        float vals[8];
        float m = -CUDART_INF_F;
#pragma unroll
        for (int q = 0; q < 8; q++) {
            vals[q] = dt_sh[w][lane + q * 32];
            m = fmaxf(m, vals[q]);
        }
#pragma unroll
        for (int o = 16; o > 0; o >>= 1)
            m = fmaxf(m, __shfl_xor_sync(0xFFFFFFFFu, m, o));
        float sum = 0.0f;
#pragma unroll
        for (int q = 0; q < 8; q++) sum += __expf(vals[q] - m);
#pragma unroll
        for (int o = 16; o > 0; o >>= 1)
            sum += __shfl_xor_sync(0xFFFFFFFFu, sum, o);
        if (lane == 0) logZ[w] = m + logf(sum);
    }
    __syncthreads();

    // out[b][s=j][t0..t0+7], contiguous 8 floats -> 2x float4
    float* op = out + (b * SRC + j) * TGT + t0;
    float4 o0, o1;
    o0.x = dt_sh[0][j] - logZ[0];
    o0.y = dt_sh[1][j] - logZ[1];
    o0.z = dt_sh[2][j] - logZ[2];
    o0.w = dt_sh[3][j] - logZ[3];
    o1.x = dt_sh[4][j] - logZ[4];
    o1.y = dt_sh[5][j] - logZ[5];
    o1.z = dt_sh[6][j] - logZ[6];
    o1.w = dt_sh[7][j] - logZ[7];
    ((float4*)op)[0] = o0;
    ((float4*)op)[1] = o1;
}

// ---------------- launch ----------------
extern "C" void kernel_launch(void* const* d_in, const int* in_sizes, int n_in,
                              void* d_out, int out_size)
{
    const float* dec  = (const float*)d_in[0];   // [8,256,512]
    const float* enc  = (const float*)d_in[1];   // [8,256,512]
    const int*   lens = (const int*)  d_in[2];   // [8]
    const float* W1   = (const float*)d_in[3];   // [512,256]
    const float* W2   = (const float*)d_in[4];   // [512,256]
    const float* vt   = (const float*)d_in[5];   // [256]
    float* out = (float*)d_out;                  // [8,256,256] = [B,src,tgt]

    dim3 g1(LDIM / BN, (NB * TGT) / BM, 2);      // (4, 32, 2)
    proj_kernel<<<g1, 256>>>(dec, enc, W1, W2);

    dim3 g2(TGT / TT, NB);                       // (32, 8)
    score_kernel<<<g2, 256>>>(lens, vt, out);
}

// round 3
// speedup vs baseline: 1.1230x; 1.1230x over previous
#include <cuda_runtime.h>
#include <cuda_fp16.h>
#include <math_constants.h>

#define D_MODEL 512
#define SRC 256
#define TGT 256
#define LDIM 256
#define L2DIM 128   // half2-packed L
#define NB 8

typedef unsigned int u32;

// ---------------- scratch (half2-packed projections) ----------------
__device__ u32 g_dt_h[NB * TGT * L2DIM];   // [2048][128] half2 over l
__device__ u32 g_et_h[NB * SRC * L2DIM];

static __device__ __forceinline__ __half2 u2h(u32 x) {
    __half2 h; *reinterpret_cast<u32*>(&h) = x; return h;
}
static __device__ __forceinline__ u32 h2u(__half2 h) {
    return *reinterpret_cast<u32*>(&h);
}

// ---------------- kernel 1: dual projection GEMM (fp32 FFMA) --------
#define BM 64
#define BN 64
#define BK 16

__global__ __launch_bounds__(256) void proj_kernel(
    const float* __restrict__ dec, const float* __restrict__ enc,
    const float* __restrict__ W1,  const float* __restrict__ W2)
{
    const float* A;
    const float* W;
    u32* C;
    if (blockIdx.z == 0) { A = dec; W = W1; C = g_dt_h; }
    else                 { A = enc; W = W2; C = g_et_h; }

    __shared__ float As[BK][68];
    __shared__ float Bs[BK][BN];

    const int tid = threadIdx.x;
    const int m0 = blockIdx.y * BM;
    const int n0 = blockIdx.x * BN;
    const int tx = tid & 15;
    const int ty = tid >> 4;

    const int am = tid >> 2;
    const int ak = (tid & 3) * 4;
    const int bk = tid >> 4;
    const int bn = (tid & 15) * 4;

    float acc[4][4];
#pragma unroll
    for (int i = 0; i < 4; i++)
#pragma unroll
        for (int j = 0; j < 4; j++) acc[i][j] = 0.0f;

    for (int k0 = 0; k0 < D_MODEL; k0 += BK) {
        float4 av = *(const float4*)(A + (m0 + am) * D_MODEL + k0 + ak);
        float4 bv = *(const float4*)(W + (k0 + bk) * LDIM + n0 + bn);
        As[ak + 0][am] = av.x;
        As[ak + 1][am] = av.y;
        As[ak + 2][am] = av.z;
        As[ak + 3][am] = av.w;
        *(float4*)&Bs[bk][bn] = bv;
        __syncthreads();
#pragma unroll
        for (int k = 0; k < BK; k++) {
            float4 a = *(const float4*)&As[k][ty * 4];
            float4 b = *(const float4*)&Bs[k][tx * 4];
            acc[0][0] = fmaf(a.x, b.x, acc[0][0]);
            acc[0][1] = fmaf(a.x, b.y, acc[0][1]);
            acc[0][2] = fmaf(a.x, b.z, acc[0][2]);
            acc[0][3] = fmaf(a.x, b.w, acc[0][3]);
            acc[1][0] = fmaf(a.y, b.x, acc[1][0]);
            acc[1][1] = fmaf(a.y, b.y, acc[1][1]);
            acc[1][2] = fmaf(a.y, b.z, acc[1][2]);
            acc[1][3] = fmaf(a.y, b.w, acc[1][3]);
            acc[2][0] = fmaf(a.z, b.x, acc[2][0]);
            acc[2][1] = fmaf(a.z, b.y, acc[2][1]);
            acc[2][2] = fmaf(a.z, b.z, acc[2][2]);
            acc[2][3] = fmaf(a.z, b.w, acc[2][3]);
            acc[3][0] = fmaf(a.w, b.x, acc[3][0]);
            acc[3][1] = fmaf(a.w, b.y, acc[3][1]);
            acc[3][2] = fmaf(a.w, b.z, acc[3][2]);
            acc[3][3] = fmaf(a.w, b.w, acc[3][3]);
        }
        __syncthreads();
    }

    // epilogue: pack to half2 pairs over n (= l) and store
#pragma unroll
    for (int i = 0; i < 4; i++) {
        __half2 h0 = __floats2half2_rn(acc[i][0], acc[i][1]);
        __half2 h1 = __floats2half2_rn(acc[i][2], acc[i][3]);
        uint2 o;
        o.x = h2u(h0);
        o.y = h2u(h1);
        *(uint2*)(C + (m0 + ty * 4 + i) * L2DIM + ((n0 + tx * 4) >> 1)) = o;
    }
}

// ---------------- kernel 2: fused half2 score + mask + log_softmax --
#define TT 8

__global__ __launch_bounds__(256) void score_kernel(
    const int* __restrict__ lens, const float* __restrict__ vt,
    float* __restrict__ out)
{
    __shared__ u32   dt_sh[TT * L2DIM];       // 4KB, half2 packed
    __shared__ u32   et_sh[16][SRC];          // 16KB, transposed chunk (16 l-pairs)
    __shared__ float score_sh[TT][SRC];       // 8KB
    __shared__ u32   vt_sh[L2DIM];            // 512B
    __shared__ float logZ[TT];

    const int b  = blockIdx.y;
    const int t0 = blockIdx.x * TT;
    const int j  = threadIdx.x;               // s index

    if (j < L2DIM) {
        float2 v = ((const float2*)vt)[j];
        vt_sh[j] = h2u(__floats2half2_rn(v.x, v.y));
    }
    // dt tile: 8 rows x 128 u32 = 256 uint4, one per thread
    ((uint4*)dt_sh)[j] = ((const uint4*)(g_dt_h + (b * TGT + t0) * L2DIM))[j];

    float2 acc[TT];
#pragma unroll
    for (int t = 0; t < TT; t++) acc[t] = make_float2(0.0f, 0.0f);

    const uint4* et4 = (const uint4*)(g_et_h + (b * SRC + j) * L2DIM);

#pragma unroll 1
    for (int ch = 0; ch < 8; ch++) {
        __syncthreads();   // protects et_sh reuse (and initial dt/vt visibility)
        uint4 e[4];
#pragma unroll
        for (int q = 0; q < 4; q++) e[q] = et4[ch * 4 + q];
#pragma unroll
        for (int q = 0; q < 4; q++) {
            et_sh[q * 4 + 0][j] = e[q].x;
            et_sh[q * 4 + 1][j] = e[q].y;
            et_sh[q * 4 + 2][j] = e[q].z;
            et_sh[q * 4 + 3][j] = e[q].w;
        }
        __syncthreads();

#pragma unroll
        for (int p = 0; p < 16; p += 4) {
            __half2 acch[TT];
#pragma unroll
            for (int t = 0; t < TT; t++) acch[t] = u2h(0u);
#pragma unroll
            for (int q = 0; q < 4; q++) {
                const int c2 = p + q;
                const __half2 e2 = u2h(et_sh[c2][j]);
                const __half2 v2 = u2h(vt_sh[ch * 16 + c2]);
#pragma unroll
                for (int t = 0; t < TT; t++) {
                    __half2 x2 = __hadd2(u2h(dt_sh[t * L2DIM + ch * 16 + c2]), e2);
                    u32 th;
                    asm("tanh.approx.f16x2 %0, %1;" : "=r"(th) : "r"(h2u(x2)));
                    acch[t] = __hfma2(v2, u2h(th), acch[t]);
                }
            }
            // fold fp16 chunk accumulators into fp32
#pragma unroll
            for (int t = 0; t < TT; t++) {
                acc[t].x += __low2float(acch[t]);
                acc[t].y += __high2float(acch[t]);
            }
        }
    }

    const float mterm = logf(((j < lens[b]) ? 1.0f : 0.0f) + 1e-8f);

#pragma unroll
    for (int t = 0; t < TT; t++)
        score_sh[t][j] = acc[t].x + acc[t].y + mterm;
    __syncthreads();

    // warp w reduces score row t=w -> logZ[w]
    const int w = j >> 5, lane = j & 31;
    {
        float vals[8];
        float m = -CUDART_INF_F;
#pragma unroll
        for (int q = 0; q < 8; q++) {
            vals[q] = score_sh[w][lane + q * 32];
            m = fmaxf(m, vals[q]);
        }
#pragma unroll
        for (int o = 16; o > 0; o >>= 1)
            m = fmaxf(m, __shfl_xor_sync(0xFFFFFFFFu, m, o));
        float sum = 0.0f;
#pragma unroll
        for (int q = 0; q < 8; q++) sum += __expf(vals[q] - m);
#pragma unroll
        for (int o = 16; o > 0; o >>= 1)
            sum += __shfl_xor_sync(0xFFFFFFFFu, sum, o);
        if (lane == 0) logZ[w] = m + logf(sum);
    }
    __syncthreads();

    // out[b][s=j][t0..t0+7]
    float* op = out + (b * SRC + j) * TGT + t0;
    float4 o0, o1;
    o0.x = score_sh[0][j] - logZ[0];
    o0.y = score_sh[1][j] - logZ[1];
    o0.z = score_sh[2][j] - logZ[2];
    o0.w = score_sh[3][j] - logZ[3];
    o1.x = score_sh[4][j] - logZ[4];
    o1.y = score_sh[5][j] - logZ[5];
    o1.z = score_sh[6][j] - logZ[6];
    o1.w = score_sh[7][j] - logZ[7];
    ((float4*)op)[0] = o0;
    ((float4*)op)[1] = o1;
}

// ---------------- launch ----------------
extern "C" void kernel_launch(void* const* d_in, const int* in_sizes, int n_in,
                              void* d_out, int out_size)
{
    const float* dec  = (const float*)d_in[0];
    const float* enc  = (const float*)d_in[1];
    const int*   lens = (const int*)  d_in[2];
    const float* W1   = (const float*)d_in[3];
    const float* W2   = (const float*)d_in[4];
    const float* vt   = (const float*)d_in[5];
    float* out = (float*)d_out;

    dim3 g1(LDIM / BN, (NB * TGT) / BM, 2);
    proj_kernel<<<g1, 256>>>(dec, enc, W1, W2);

    dim3 g2(TGT / TT, NB);
    score_kernel<<<g2, 256>>>(lens, vt, out);
}